// round 9
// baseline (speedup 1.0000x reference)
#include <cuda_runtime.h>
#include <math_constants.h>
#include <cstdint>

// Problem constants
#define B_     32
#define HS_    512
#define C_     256
#define HW_    4096
#define A_     256
#define CHUNK  32                 // pixels per sub-tile in the pass
#define PITER  4                  // sub-tiles per block (online softmax)
#define BLKPIX (CHUNK * PITER)    // 128 pixels per block
#define NCHUNK (HW_ / BLKPIX)     // 32 chunks per batch (== warp size)
#define KSPLIT 8                  // split-K factor for wh

// Scratch (allocation-free rule: __device__ globals)
__device__ float g_whp[B_ * KSPLIT * A_];    // split-K partials of wh
__device__ float g_v[B_ * C_];               // v[b,c] = W_fm @ wh[b]
__device__ float g_m[B_ * NCHUNK];           // per-chunk running max
__device__ float g_s[B_ * NCHUNK];           // per-chunk exp-sum
__device__ float g_part[B_ * NCHUNK * C_];   // per-chunk partial context (1 MB)

// ---------------------------------------------------------------------------
// K1a: split-K partial of wh[b] = h_dec[b] @ W_h.
// grid = (B_, KSPLIT) = 256 blocks, block = 256.
// ---------------------------------------------------------------------------
__global__ __launch_bounds__(256) void prep_a_kernel(
    const float* __restrict__ h_dec,  // (B, HS)
    const float* __restrict__ W_h)    // (HS, A)
{
    const int b   = blockIdx.x;
    const int s   = blockIdx.y;
    const int tid = threadIdx.x;
    const int hs0 = s * (HS_ / KSPLIT);     // 64 rows per split

    __shared__ float sh[HS_ / KSPLIT];
    if (tid < HS_ / KSPLIT)
        sh[tid] = h_dec[b * HS_ + hs0 + tid];
    __syncthreads();

    float acc = 0.f;
    #pragma unroll 8
    for (int hs = 0; hs < HS_ / KSPLIT; ++hs)
        acc = fmaf(sh[hs], W_h[(size_t)(hs0 + hs) * A_ + tid], acc);  // coalesced
    g_whp[(b * KSPLIT + s) * A_ + tid] = acc;
}

// ---------------------------------------------------------------------------
// K1b: fold split-K partials + b_h -> wh; then v[b,c] = W_fm[c,:]·wh.
// grid = (B_, 2) = 64 blocks; 2 threads per channel, each half of A.
// ---------------------------------------------------------------------------
__global__ __launch_bounds__(256) void prep_b_kernel(
    const float* __restrict__ b_h,    // (A)
    const float* __restrict__ W_fm)   // (C, A)
{
    const int b   = blockIdx.x;
    const int cy  = blockIdx.y;       // channel half: 0 or 1
    const int tid = threadIdx.x;

    __shared__ float wh[A_];
    __shared__ float s2[256];

    float acc = b_h[tid];
    #pragma unroll
    for (int s = 0; s < KSPLIT; ++s)
        acc += g_whp[(b * KSPLIT + s) * A_ + tid];   // coalesced
    wh[tid] = acc;
    __syncthreads();

    const int c_local = tid >> 1;              // 0..127
    const int half    = tid & 1;               // A half
    const int c       = cy * 128 + c_local;
    const int a0      = half * (A_ / 2);       // 128

    const float4* wrow = (const float4*)(W_fm + (size_t)c * A_ + a0);
    float vv = 0.f;
    #pragma unroll 8
    for (int a4 = 0; a4 < A_ / 8; ++a4) {      // 32 float4
        float4 w4 = wrow[a4];
        vv = fmaf(w4.x, wh[a0 + a4 * 4 + 0],
             fmaf(w4.y, wh[a0 + a4 * 4 + 1],
             fmaf(w4.z, wh[a0 + a4 * 4 + 2],
             fmaf(w4.w, wh[a0 + a4 * 4 + 3], vv))));
    }
    s2[tid] = vv;
    __syncthreads();

    if (tid < 128)
        g_v[b * C_ + cy * 128 + tid] = s2[2 * tid] + s2[2 * tid + 1];
}

// ---------------------------------------------------------------------------
// K2: main single-DRAM-pass kernel, online softmax over PITER sub-tiles.
// grid = (NCHUNK, B) = 1024 blocks, block = 256.
// ONE barrier per iteration: s_red is double-buffered, and every warp
// redundantly folds the full 32-pixel score set (lane = pixel), keeping an
// identical running (m, s) per warp — no cross-warp broadcast needed.
// ---------------------------------------------------------------------------
__global__ __launch_bounds__(256) void pass_kernel(const float* __restrict__ fm)
{
    __shared__ float s_v[C_];
    __shared__ float s_red[2][CHUNK * 33];   // double-buffered [pixel][group]
    __shared__ float s_part[C_ * 9];         // [channel][quad] padded

    const int b     = blockIdx.y;
    const int q     = blockIdx.x;
    const int p0    = q * BLKPIX;
    const int tid   = threadIdx.x;
    const int lane  = tid & 31;
    const int j     = tid & 7;            // quad (4 pixels)
    const int g     = tid >> 3;           // channel group 0..31
    const int pbase = j * 4;

    s_v[tid] = g_v[b * C_ + tid];

    const float* fmb = fm + (size_t)b * C_ * HW_ + p0 + j * 4;

    // prefetch sub-tile 0
    float4 val[8], valn[8];
    #pragma unroll
    for (int k = 0; k < 8; ++k)
        val[k] = __ldcs((const float4*)(fmb + (size_t)(g + 32 * k) * HW_));

    __syncthreads();   // s_v ready

    float ctx[8];
    #pragma unroll
    for (int k = 0; k < 8; ++k) ctx[k] = 0.f;
    float m_run = -CUDART_INF_F;   // identical in every thread
    float s_run = 0.f;

    #pragma unroll
    for (int it = 0; it < PITER; ++it) {
        const int buf = it & 1;

        // prefetch next sub-tile (issues before the barrier below)
        if (it + 1 < PITER) {
            #pragma unroll
            for (int k = 0; k < 8; ++k)
                valn[k] = __ldcs((const float4*)(fmb + (size_t)(g + 32 * k) * HW_
                                                 + (it + 1) * CHUNK));
        }

        // score partials for my 4 pixels over my 8 channels
        float sc0 = 0.f, sc1 = 0.f, sc2 = 0.f, sc3 = 0.f;
        #pragma unroll
        for (int k = 0; k < 8; ++k) {
            const float vr = s_v[g + 32 * k];
            sc0 = fmaf(val[k].x, vr, sc0);
            sc1 = fmaf(val[k].y, vr, sc1);
            sc2 = fmaf(val[k].z, vr, sc2);
            sc3 = fmaf(val[k].w, vr, sc3);
        }
        s_red[buf][(pbase + 0) * 33 + g] = sc0;
        s_red[buf][(pbase + 1) * 33 + g] = sc1;
        s_red[buf][(pbase + 2) * 33 + g] = sc2;
        s_red[buf][(pbase + 3) * 33 + g] = sc3;
        __syncthreads();   // (also protects buf reuse two iterations apart)

        // EVERY warp: lane = pixel. Fold 32 group partials (stride 33: no
        // bank conflicts), then warp-local max/exp/sum — identical results
        // in all warps, so no broadcast or second barrier.
        float sc = 0.f;
        #pragma unroll
        for (int gg = 0; gg < 32; ++gg)
            sc += s_red[buf][lane * 33 + gg];

        float m_i = sc;
        #pragma unroll
        for (int o = 16; o > 0; o >>= 1)
            m_i = fmaxf(m_i, __shfl_xor_sync(0xffffffffu, m_i, o));

        const float m_new     = fmaxf(m_run, m_i);
        const float scale_old = __expf(m_run - m_new);   // 0 on first iter

        const float w = __expf(sc - m_new);

        float ssum = w;
        #pragma unroll
        for (int o = 16; o > 0; o >>= 1)
            ssum += __shfl_xor_sync(0xffffffffu, ssum, o);

        s_run = fmaf(s_run, scale_old, ssum);
        m_run = m_new;

        // weights for my quad via shuffle from lanes pbase..pbase+3
        const float w0 = __shfl_sync(0xffffffffu, w, pbase + 0);
        const float w1 = __shfl_sync(0xffffffffu, w, pbase + 1);
        const float w2 = __shfl_sync(0xffffffffu, w, pbase + 2);
        const float w3 = __shfl_sync(0xffffffffu, w, pbase + 3);

        #pragma unroll
        for (int k = 0; k < 8; ++k) {
            float a = fmaf(val[k].x, w0,
                      fmaf(val[k].y, w1,
                      fmaf(val[k].z, w2, val[k].w * w3)));
            ctx[k] = fmaf(ctx[k], scale_old, a);
        }

        if (it + 1 < PITER) {
            #pragma unroll
            for (int k = 0; k < 8; ++k) val[k] = valn[k];
        }
    }

    if (tid == 0) {
        g_m[b * NCHUNK + q] = m_run;
        g_s[b * NCHUNK + q] = s_run;
    }

    // fold quads per channel, coalesced store
    #pragma unroll
    for (int k = 0; k < 8; ++k)
        s_part[(g + 32 * k) * 9 + j] = ctx[k];
    __syncthreads();

    float acc = 0.f;
    #pragma unroll
    for (int jj = 0; jj < 8; ++jj)
        acc += s_part[tid * 9 + jj];
    g_part[((size_t)(b * NCHUNK + q)) * C_ + tid] = acc;
}

// ---------------------------------------------------------------------------
// K3: combine, single kernel. grid = B_, block = 256.
// NCHUNK == 32 == warp size: lane l owns chunk l. Each warp redundantly
// computes M, Z, coef (no smem, no barrier); coefs broadcast by shuffle.
// Per thread: 32 coalesced L2 loads of g_part (L2-resident, 1 MB).
// ---------------------------------------------------------------------------
__global__ __launch_bounds__(256) void combine_kernel(float* __restrict__ out)
{
    const int b    = blockIdx.x;
    const int tid  = threadIdx.x;
    const int lane = tid & 31;

    const float mv = g_m[b * NCHUNK + lane];   // broadcast across warps (L2)
    const float sv = g_s[b * NCHUNK + lane];

    float M = mv;
    #pragma unroll
    for (int o = 16; o > 0; o >>= 1)
        M = fmaxf(M, __shfl_xor_sync(0xffffffffu, M, o));

    const float e = __expf(mv - M);
    float Z = sv * e;
    #pragma unroll
    for (int o = 16; o > 0; o >>= 1)
        Z += __shfl_xor_sync(0xffffffffu, Z, o);

    const float coef = e / Z;                  // lane l: coef of chunk l

    float acc = 0.f;
    const float* base = g_part + (size_t)b * NCHUNK * C_;
    #pragma unroll
    for (int qq = 0; qq < NCHUNK; ++qq)
        acc = fmaf(base[qq * C_ + tid],        // coalesced, MLP=32
                   __shfl_sync(0xffffffffu, coef, qq), acc);
    out[b * C_ + tid] = acc;
}

// ---------------------------------------------------------------------------
// Launch. Input order (metadata): h_dec, fm, W_fm, b_fm(unused), W_h, b_h
// ---------------------------------------------------------------------------
extern "C" void kernel_launch(void* const* d_in, const int* in_sizes, int n_in,
                              void* d_out, int out_size)
{
    const float* h_dec = (const float*)d_in[0];
    const float* fm    = (const float*)d_in[1];
    const float* W_fm  = (const float*)d_in[2];
    // d_in[3] = b_fm — cancels in softmax, unused
    const float* W_h   = (const float*)d_in[4];
    const float* b_h   = (const float*)d_in[5];
    float* out = (float*)d_out;

    prep_a_kernel<<<dim3(B_, KSPLIT), 256>>>(h_dec, W_h);
    prep_b_kernel<<<dim3(B_, 2), 256>>>(b_h, W_fm);
    pass_kernel<<<dim3(NCHUNK, B_), 256>>>(fm);
    combine_kernel<<<B_, 256>>>(out);
}